// round 11
// baseline (speedup 1.0000x reference)
#include <cuda_runtime.h>
#include <cuda_fp16.h>
#include <stdint.h>

#define BB    128
#define TT    512
#define HH    256
#define LL    6
#define INW   128
#define FOURH 1024
#define NC    16
#define GRIDB (LL*NC)      // 96
#define NTH   256
#define KMAX  512
#define SIWC  (KMAX + 8)   // 520 halfs row stride (weights AND A tile)
// ws 64*520*2 + A 128*520*2 + gbuf 256*64 = 66560 + 133120 + 16384 = 216064
#define SMEM_BYTES (64*SIWC*2 + 128*SIWC*2 + 256*64)

// ---------------- persistent device state ----------------
__device__ __align__(256) __half d_wpack[(size_t)LL*FOURH*KMAX];  // rows: [Whh(256) | Wih(din)]
__device__ __align__(256) float  d_bpack[LL*FOURH];
__device__ __align__(256) __half d_xh[(size_t)BB*TT*INW];
__device__ __align__(256) __half d_hring[LL*4*BB*HH];             // 4-slot h ring per layer
__device__ unsigned g_arrive[LL];

__device__ __forceinline__ int hring_off(int l, int slot, int b, int k){
  return ((l*4 + slot)*BB + b)*HH + k;
}

// ---------------- prep kernels ----------------
__global__ void prep_pack(const float* __restrict__ w_ih0,
                          const float* __restrict__ w_ih,
                          const float* __restrict__ w_hh,
                          const float* __restrict__ b_ih,
                          const float* __restrict__ b_hh){
  long long idx = (long long)blockIdx.x*blockDim.x + threadIdx.x;
  if (idx >= (long long)LL*FOURH*KMAX) return;
  int k = (int)(idx % KMAX);
  int p = (int)((idx / KMAX) % FOURH);
  int l = (int)(idx / ((long long)KMAX*FOURH));
  int cid = p >> 6, rr = p & 63, gate = rr >> 4, jj = rr & 15;
  int srow = gate*HH + cid*16 + jj;
  int din  = (l == 0) ? INW : HH;
  float v = 0.f;
  if (k < HH)             v = w_hh[((size_t)l*FOURH + srow)*HH + k];
  else if (k < HH + din)  v = (l == 0) ? w_ih0[srow*INW + (k - HH)]
                                       : w_ih[((size_t)(l-1)*FOURH + srow)*HH + (k - HH)];
  d_wpack[idx] = __float2half(v);
  if (k == 0) d_bpack[l*FOURH + p] = b_ih[l*FOURH + srow] + b_hh[l*FOURH + srow];
}

__global__ void prep_x(const float* __restrict__ x){
  long long i = (long long)blockIdx.x*blockDim.x + threadIdx.x;
  if (i < (long long)BB*TT*INW) d_xh[i] = __float2half(x[i]);
}

__global__ void prep_init(const float* __restrict__ h0){
  int i = blockIdx.x*blockDim.x + threadIdx.x;
  if (i < LL*BB*HH){
    int l = i/(BB*HH), rem = i%(BB*HH);
    d_hring[hring_off(l, 0, rem/HH, rem%HH)] = __float2half(h0[i]);
  }
  if (i == 0){
    #pragma unroll
    for (int l = 0; l < LL; l++) g_arrive[l] = 0u;
  }
}

// ---------------- low-level helpers ----------------
__device__ __forceinline__ unsigned smem_u32(const void* p){
  unsigned a;
  asm("{ .reg .u64 t; cvta.to.shared.u64 t, %1; cvt.u32.u64 %0, t; }" : "=r"(a) : "l"(p));
  return a;
}
__device__ __forceinline__ void cp_async16(uint32_t dst, const void* src){
  asm volatile("cp.async.cg.shared.global [%0], [%1], 16;" :: "r"(dst), "l"(src));
}
__device__ __forceinline__ void bar_sync(int id, int cnt){
  asm volatile("bar.sync %0, %1;" :: "r"(id), "r"(cnt) : "memory");
}
__device__ __forceinline__ void ldsm_x4(unsigned addr, unsigned& r0, unsigned& r1,
                                        unsigned& r2, unsigned& r3){
  asm volatile("ldmatrix.sync.aligned.m8n8.x4.shared.b16 {%0,%1,%2,%3}, [%4];\n"
               : "=r"(r0), "=r"(r1), "=r"(r2), "=r"(r3) : "r"(addr));
}
__device__ __forceinline__ void mma_16816(float d[4], const unsigned a[4], const unsigned b0,
                                          const unsigned b1){
  asm volatile("mma.sync.aligned.m16n8k16.row.col.f32.f16.f16.f32 "
               "{%0,%1,%2,%3}, {%4,%5,%6,%7}, {%8,%9}, {%0,%1,%2,%3};\n"
               : "+f"(d[0]), "+f"(d[1]), "+f"(d[2]), "+f"(d[3])
               : "r"(a[0]), "r"(a[1]), "r"(a[2]), "r"(a[3]), "r"(b0), "r"(b1));
}
__device__ __forceinline__ float tanh_fast(float x){
  float r; asm("tanh.approx.f32 %0, %1;" : "=f"(r) : "f"(x)); return r;
}
__device__ __forceinline__ float sig_fast(float x){
  return fmaf(tanh_fast(0.5f*x), 0.5f, 0.5f);
}
__device__ __forceinline__ void wait_ge(unsigned* p, unsigned target){
  unsigned v;
  #pragma unroll 1
  do {
    asm volatile("ld.acquire.gpu.global.u32 %0, [%1];" : "=r"(v) : "l"(p) : "memory");
  } while (v < target);
}
__device__ __forceinline__ void arrive_release(unsigned* p){
  asm volatile("red.release.gpu.global.add.u32 [%0], %1;" :: "l"(p), "r"(1u) : "memory");
}
__device__ __forceinline__ void st_cg_u32(void* p, unsigned v){
  asm volatile("st.global.cg.u32 [%0], %1;" :: "l"(p), "r"(v) : "memory");
}
__device__ __forceinline__ void sts128(uint32_t addr, unsigned a, unsigned b,
                                       unsigned c, unsigned d){
  asm volatile("st.shared.v4.b32 [%0], {%1,%2,%3,%4};"
               :: "r"(addr), "r"(a), "r"(b), "r"(c), "r"(d) : "memory");
}
__device__ __forceinline__ void lds128(uint32_t addr, unsigned& a, unsigned& b,
                                       unsigned& c, unsigned& d){
  asm volatile("ld.shared.v4.b32 {%0,%1,%2,%3}, [%4];"
               : "=r"(a), "=r"(b), "=r"(c), "=r"(d) : "r"(addr));
}
__device__ __forceinline__ unsigned pack2(float a, float b){
  __half2 h = __floats2half2_rn(a, b);
  return *(unsigned*)&h;
}

// one 4-k-iter GEMM block over cols [kb*64, kb*64+64)
#define GEMM_BLK(ACC, A0, A1, KB)                                              \
  _Pragma("unroll")                                                            \
  for (int ki = 4*(KB); ki < 4*(KB)+4; ki++){                                  \
    const unsigned kofs = (unsigned)(ki*32);                                   \
    unsigned a0[4], a1[4], b0[4], b1[4], b2[4], b3[4];                         \
    ldsm_x4((A0) + kofs, a0[0], a0[1], a0[2], a0[3]);                          \
    ldsm_x4((A1) + kofs, a1[0], a1[1], a1[2], a1[3]);                          \
    ldsm_x4(bX[0] + kofs, b0[0], b0[1], b0[2], b0[3]);                         \
    ldsm_x4(bX[1] + kofs, b1[0], b1[1], b1[2], b1[3]);                         \
    ldsm_x4(bX[2] + kofs, b2[0], b2[1], b2[2], b2[3]);                         \
    ldsm_x4(bX[3] + kofs, b3[0], b3[1], b3[2], b3[3]);                         \
    _Pragma("unroll")                                                          \
    for (int mt = 0; mt < 2; mt++){                                            \
      const unsigned* a = mt ? a1 : a0;                                        \
      mma_16816((ACC)[mt][0], a, b0[0], b0[1]);                                \
      mma_16816((ACC)[mt][1], a, b1[0], b1[1]);                                \
      mma_16816((ACC)[mt][2], a, b0[2], b0[3]);                                \
      mma_16816((ACC)[mt][3], a, b1[2], b1[3]);                                \
      mma_16816((ACC)[mt][4], a, b2[0], b2[1]);                                \
      mma_16816((ACC)[mt][5], a, b3[0], b3[1]);                                \
      mma_16816((ACC)[mt][6], a, b2[2], b2[3]);                                \
      mma_16816((ACC)[mt][7], a, b3[2], b3[3]);                                \
    }                                                                          \
  }

// ---------------- per-layer persistent worker ----------------
// REC warps (0-3): poll, 4-chunk staged own-h, recurrent GEMM (all 128 rows),
//   dump mt=1 half (fp16), epilogue mt=0 cells.
// INP warps (4-7): stage+GEMM input contribution (all 128 rows), dump mt=0
//   half, epilogue mt=1 cells. Both halves epilogue in parallel after bar1.
template<int DINA>
__device__ __forceinline__ void run_layer(const int l, const int cid,
                                          const float* __restrict__ c0,
                                          float* __restrict__ out, char* smem_raw)
{
  constexpr int SIW = SIWC;
  constexpr int NI  = DINA/16;
  constexpr int CHI = DINA/8;
  __half* ws = (__half*)smem_raw;            // [64][520]
  __half* A  = ws + 64*SIW;                  // [128][520]
  uint32_t* gbuf = (uint32_t*)(A + 128*SIW); // 256 slots * 64B
  const int tid = threadIdx.x;

  {
    const __half* src = d_wpack + ((size_t)(l*FOURH + cid*64))*KMAX;
    for (int v = tid; v < 64*64; v += NTH){
      int r = v >> 6, kk = (v & 63)*8;
      *(uint4*)(ws + r*SIW + kk) = *(const uint4*)(src + (size_t)r*KMAX + kk);
    }
  }

  const int w = tid >> 5, lane = tid & 31;
  const int q = lane >> 3, rs = lane & 7;
  const int gid = lane >> 2, ct = lane & 3;

  unsigned bX[4];
  {
    const int Xs[4] = {0, 8, 32, 40};
    #pragma unroll
    for (int i = 0; i < 4; i++)
      bX[i] = smem_u32(ws + (Xs[i] + rs + ((q>>1)<<4))*SIW + ((q&1)<<3));
  }
  const uint32_t Abase = smem_u32(A);
  const uint32_t gdst = smem_u32(gbuf) + (unsigned)tid*64u;
  const uint32_t gsrc = smem_u32(gbuf) + (unsigned)(tid ^ 128)*64u;

  // biases for this thread's 8 epilogue cells (4 gates x jh2 x cc2)
  float bias[16];
  #pragma unroll
  for (int g = 0; g < 4; g++)
    #pragma unroll
    for (int jh = 0; jh < 2; jh++)
      #pragma unroll
      for (int cc = 0; cc < 2; cc++)
        bias[g*4 + jh*2 + cc] = d_bpack[l*FOURH + cid*64 + g*16 + jh*8 + ct*2 + cc];

  // epilogue row base: REC owns mt=0 rows, INP owns mt=1 rows of warp (w&3)
  const int myrow0 = (w & 3)*32 + ((w >> 2) ? 16 : 0) + gid;

  float creg[8];
  #pragma unroll
  for (int rr = 0; rr < 2; rr++)
    #pragma unroll
    for (int jh = 0; jh < 2; jh++)
      #pragma unroll
      for (int cc = 0; cc < 2; cc++)
        creg[rr*4 + jh*2 + cc] =
          c0[(l*BB + myrow0 + rr*8)*HH + cid*16 + jh*8 + ct*2 + cc];

  __syncthreads();

  if (w < 4){
    // ========== REC: critical path ==========
    const unsigned aB0 = smem_u32(A + (w*32 + rs + ((q&1)<<3))*SIW + ((q>>1)<<3));
    const unsigned aB1 = aB0 + (unsigned)(32*SIW);

    for (int t = 0; t < TT; t++){
      if (tid == 0){
        if (t > 0)               wait_ge(&g_arrive[l],   16u*(unsigned)t);
        if (l < LL-1 && t >= 3)  wait_ge(&g_arrive[l+1], 16u*(unsigned)(t-2));
      }
      bar_sync(4, 128);

      // stage own h_{t-1} in 4 K-chunks (progressive overlap with GEMM)
      const __half* hs = d_hring + hring_off(l, t&3, 0, 0);
      #pragma unroll
      for (int cch = 0; cch < 4; cch++){
        for (int v = tid; v < 1024; v += 128){
          int r = v >> 3, kk = cch*64 + (v & 7)*8;
          cp_async16(Abase + (uint32_t)(r*SIW + kk)*2u, hs + r*HH + kk);
        }
        asm volatile("cp.async.commit_group;");
      }

      float acc[2][8][4];
      #pragma unroll
      for (int i = 0; i < 2; i++)
        #pragma unroll
        for (int j = 0; j < 8; j++)
          #pragma unroll
          for (int e = 0; e < 4; e++) acc[i][j][e] = 0.f;

      asm volatile("cp.async.wait_group 3;" ::: "memory");
      bar_sync(5, 128);
      GEMM_BLK(acc, aB0, aB1, 0)
      asm volatile("cp.async.wait_group 2;" ::: "memory");
      bar_sync(5, 128);
      GEMM_BLK(acc, aB0, aB1, 1)
      asm volatile("cp.async.wait_group 1;" ::: "memory");
      bar_sync(5, 128);
      GEMM_BLK(acc, aB0, aB1, 2)
      asm volatile("cp.async.wait_group 0;" ::: "memory");
      bar_sync(5, 128);
      GEMM_BLK(acc, aB0, aB1, 3)

      // dump mt=1 half (rows w*32+16..+31) as fp16
      #pragma unroll
      for (int i = 0; i < 4; i++){
        int j0 = 4*i;
        sts128(gdst + (unsigned)(i*16),
               pack2(acc[1][(j0  )>>1][((j0  )&1)*2], acc[1][(j0  )>>1][((j0  )&1)*2+1]),
               pack2(acc[1][(j0+1)>>1][((j0+1)&1)*2], acc[1][(j0+1)>>1][((j0+1)&1)*2+1]),
               pack2(acc[1][(j0+2)>>1][((j0+2)&1)*2], acc[1][(j0+2)>>1][((j0+2)&1)*2+1]),
               pack2(acc[1][(j0+3)>>1][((j0+3)&1)*2], acc[1][(j0+3)>>1][((j0+3)&1)*2+1]));
      }
      bar_sync(1, NTH);

      // read INP's mt=0 input partials; epilogue mt=0 cells
      unsigned g32[16];
      #pragma unroll
      for (int i = 0; i < 4; i++)
        lds128(gsrc + (unsigned)(i*16), g32[4*i], g32[4*i+1], g32[4*i+2], g32[4*i+3]);

      __half* hslot = d_hring + hring_off(l, (t+1)&3, 0, 0);
      #pragma unroll
      for (int rr = 0; rr < 2; rr++){
        int row = myrow0 + rr*8;
        #pragma unroll
        for (int jh = 0; jh < 2; jh++){
          float2 dI = __half22float2(*(const __half2*)&g32[(    jh)*2 + rr]);
          float2 dF = __half22float2(*(const __half2*)&g32[(2 + jh)*2 + rr]);
          float2 dG = __half22float2(*(const __half2*)&g32[(4 + jh)*2 + rr]);
          float2 dO = __half22float2(*(const __half2*)&g32[(6 + jh)*2 + rr]);
          float hv[2];
          #pragma unroll
          for (int cc = 0; cc < 2; cc++){
            int e  = rr*2 + cc;
            int ci = rr*4 + jh*2 + cc;
            float gi = acc[0][     jh][e] + (cc ? dI.y : dI.x) + bias[     jh*2 + cc];
            float gf = acc[0][2 + jh][e] + (cc ? dF.y : dF.x) + bias[ 4 + jh*2 + cc];
            float gg = acc[0][4 + jh][e] + (cc ? dG.y : dG.x) + bias[ 8 + jh*2 + cc];
            float go = acc[0][6 + jh][e] + (cc ? dO.y : dO.x) + bias[12 + jh*2 + cc];
            float c  = sig_fast(gf)*creg[ci] + sig_fast(gi)*tanh_fast(gg);
            creg[ci] = c;
            hv[cc]   = sig_fast(go)*tanh_fast(c);
          }
          int col0 = cid*16 + jh*8 + ct*2;
          st_cg_u32(hslot + row*HH + col0, pack2(hv[0], hv[1]));
          if (t == TT-1){
            out[(l*BB + row)*HH + col0    ] = hv[0];
            out[(l*BB + row)*HH + col0 + 1] = hv[1];
          }
        }
      }
      bar_sync(6, NTH);
      if (tid == 0) arrive_release(&g_arrive[l]);
    }
  } else {
    // ========== INP: input GEMM + dump + epilogue (mt=1 cells) ==========
    const int wi = w - 4;
    const unsigned aI0 = smem_u32(A + (wi*32 + rs + ((q&1)<<3))*SIW + 256 + ((q>>1)<<3));
    const unsigned aI1 = aI0 + (unsigned)(32*SIW);
    unsigned bI[4];
    #pragma unroll
    for (int i = 0; i < 4; i++) bI[i] = bX[i] + 512u;

    auto stage_input = [&](int tt){
      for (int v = tid - 128; v < 128*CHI; v += 128){
        int r = v / CHI, kk = (v - r*CHI)*8;
        const __half* src = (DINA == INW)
          ? d_xh + ((size_t)r*TT + tt)*INW + kk
          : d_hring + hring_off(l-1, (tt+1)&3, r, kk);
        cp_async16(Abase + (uint32_t)(r*SIW + 256 + kk)*2u, src);
      }
      asm volatile("cp.async.commit_group;");
      asm volatile("cp.async.wait_group 0;" ::: "memory");
    };

    if (tid == 128 && l > 0) wait_ge(&g_arrive[l-1], 16u);
    bar_sync(3, 128);
    stage_input(0);
    bar_sync(3, 128);

    for (int t = 0; t < TT; t++){
      float accI[2][8][4];
      #pragma unroll
      for (int i = 0; i < 2; i++)
        #pragma unroll
        for (int j = 0; j < 8; j++)
          #pragma unroll
          for (int e = 0; e < 4; e++) accI[i][j][e] = 0.f;

      #pragma unroll
      for (int ki = 0; ki < NI; ki++){
        const unsigned kofs = (unsigned)(ki*32);
        unsigned a0[4], a1[4], b0[4], b1[4], b2[4], b3[4];
        ldsm_x4(aI0 + kofs, a0[0], a0[1], a0[2], a0[3]);
        ldsm_x4(aI1 + kofs, a1[0], a1[1], a1[2], a1[3]);
        ldsm_x4(bI[0] + kofs, b0[0], b0[1], b0[2], b0[3]);
        ldsm_x4(bI[1] + kofs, b1[0], b1[1], b1[2], b1[3]);
        ldsm_x4(bI[2] + kofs, b2[0], b2[1], b2[2], b2[3]);
        ldsm_x4(bI[3] + kofs, b3[0], b3[1], b3[2], b3[3]);
        #pragma unroll
        for (int mt = 0; mt < 2; mt++){
          const unsigned* a = mt ? a1 : a0;
          mma_16816(accI[mt][0], a, b0[0], b0[1]);
          mma_16816(accI[mt][1], a, b1[0], b1[1]);
          mma_16816(accI[mt][2], a, b0[2], b0[3]);
          mma_16816(accI[mt][3], a, b1[2], b1[3]);
          mma_16816(accI[mt][4], a, b2[0], b2[1]);
          mma_16816(accI[mt][5], a, b3[0], b3[1]);
          mma_16816(accI[mt][6], a, b2[2], b2[3]);
          mma_16816(accI[mt][7], a, b3[2], b3[3]);
        }
      }

      // dump mt=0 half (rows wi*32..+15) as fp16
      #pragma unroll
      for (int i = 0; i < 4; i++){
        int j0 = 4*i;
        sts128(gdst + (unsigned)(i*16),
               pack2(accI[0][(j0  )>>1][((j0  )&1)*2], accI[0][(j0  )>>1][((j0  )&1)*2+1]),
               pack2(accI[0][(j0+1)>>1][((j0+1)&1)*2], accI[0][(j0+1)>>1][((j0+1)&1)*2+1]),
               pack2(accI[0][(j0+2)>>1][((j0+2)&1)*2], accI[0][(j0+2)>>1][((j0+2)&1)*2+1]),
               pack2(accI[0][(j0+3)>>1][((j0+3)&1)*2], accI[0][(j0+3)>>1][((j0+3)&1)*2+1]));
      }
      bar_sync(1, NTH);

      // read REC's mt=1 recurrent partials; epilogue mt=1 cells
      unsigned g32[16];
      #pragma unroll
      for (int i = 0; i < 4; i++)
        lds128(gsrc + (unsigned)(i*16), g32[4*i], g32[4*i+1], g32[4*i+2], g32[4*i+3]);

      __half* hslot = d_hring + hring_off(l, (t+1)&3, 0, 0);
      #pragma unroll
      for (int rr = 0; rr < 2; rr++){
        int row = myrow0 + rr*8;
        #pragma unroll
        for (int jh = 0; jh < 2; jh++){
          float2 dI = __half22float2(*(const __half2*)&g32[(    jh)*2 + rr]);
          float2 dF = __half22float2(*(const __half2*)&g32[(2 + jh)*2 + rr]);
          float2 dG = __half22float2(*(const __half2*)&g32[(4 + jh)*2 + rr]);
          float2 dO = __half22float2(*(const __half2*)&g32[(6 + jh)*2 + rr]);
          float hv[2];
          #pragma unroll
          for (int cc = 0; cc < 2; cc++){
            int e  = rr*2 + cc;
            int ci = rr*4 + jh*2 + cc;
            float gi = accI[1][     jh][e] + (cc ? dI.y : dI.x) + bias[     jh*2 + cc];
            float gf = accI[1][2 + jh][e] + (cc ? dF.y : dF.x) + bias[ 4 + jh*2 + cc];
            float gg = accI[1][4 + jh][e] + (cc ? dG.y : dG.x) + bias[ 8 + jh*2 + cc];
            float go = accI[1][6 + jh][e] + (cc ? dO.y : dO.x) + bias[12 + jh*2 + cc];
            float c  = sig_fast(gf)*creg[ci] + sig_fast(gi)*tanh_fast(gg);
            creg[ci] = c;
            hv[cc]   = sig_fast(go)*tanh_fast(c);
          }
          int col0 = cid*16 + jh*8 + ct*2;
          st_cg_u32(hslot + row*HH + col0, pack2(hv[0], hv[1]));
          if (t == TT-1){
            out[(l*BB + row)*HH + col0    ] = hv[0];
            out[(l*BB + row)*HH + col0 + 1] = hv[1];
          }
        }
      }
      bar_sync(6, NTH);

      if (t < TT-1){
        if (tid == 128 && l > 0) wait_ge(&g_arrive[l-1], 16u*(unsigned)(t+2));
        bar_sync(3, 128);
        stage_input(t+1);
        bar_sync(3, 128);
      }
    }
  }
}

__global__ void __launch_bounds__(NTH, 1)
lstm_persist(const float* __restrict__ c0, float* __restrict__ out)
{
  extern __shared__ __align__(16) char smem_raw[];
  const int l = blockIdx.x >> 4, cid = blockIdx.x & 15;
  if (l == 0) run_layer<INW>(0, cid, c0, out, smem_raw);
  else        run_layer<HH >(l, cid, c0, out, smem_raw);
}

// ---------------- launch ----------------
extern "C" void kernel_launch(void* const* d_in, const int* in_sizes, int n_in,
                              void* d_out, int out_size){
  const float* x     = (const float*)d_in[0];
  const float* h0    = (const float*)d_in[1];
  const float* c0    = (const float*)d_in[2];
  const float* w_ih0 = (const float*)d_in[3];
  const float* w_ih  = (const float*)d_in[4];
  const float* w_hh  = (const float*)d_in[5];
  const float* b_ih  = (const float*)d_in[6];
  const float* b_hh  = (const float*)d_in[7];
  float* out = (float*)d_out;

  cudaFuncSetAttribute(lstm_persist, cudaFuncAttributeMaxDynamicSharedMemorySize, SMEM_BYTES);

  prep_pack<<<(LL*FOURH*KMAX + 255)/256, 256>>>(w_ih0, w_ih, w_hh, b_ih, b_hh);
  prep_x   <<<(BB*TT*INW    + 255)/256, 256>>>(x);
  prep_init<<<(LL*BB*HH     + 255)/256, 256>>>(h0);
  lstm_persist<<<GRIDB, NTH, SMEM_BYTES>>>(c0, out);
}